// round 11
// baseline (speedup 1.0000x reference)
#include <cuda_runtime.h>
#include <cstdint>

#define B_SZ  2
#define GQ    32
#define HDIM  128
#define NH    8
#define DK    16
#define SLEN  4096
#define STILE 8
#define NT    256

typedef unsigned long long u64;

// SMEM (u64 units), total 14464 u64 = 115712 B -> 2 CTAs/SM:
//  sQ   [0,2048)      u64[(d*4+sp)*32 + g]        (Q tile; dead after B2)
//  sK   [2048,4096)   float[f*128 + d*8 + s]      (K tile; dead after B2)
//    eX  = [0,4096)   u64[(sp*32+f)*32 + g]       probs exchange (B2->B4)
//    xSt = [0,2048)   u64[(sp*16+d)*32 + g]       x staging (B4->B5)
//  sV   [4096,6144)   float[f*128 + d*8 + s]      (V tile; dead after B4)
//  sL   [6144,10240)  u64[(sp*32+f)*32 + g]       logits sums over h
//  sA   [10240,14336) same                        attn sums over h
//  sSum [14336,14464) u64[sp*32 + g]              softmax totals (red.shared,
//                     exactly 2 adds/slot -> deterministic; zeroed post-B3)
#define SQ_U64   0
#define SK_U64   2048
#define SV_U64   4096
#define SL_U64   6144
#define SA_U64   10240
#define SSUM_U64 14336
#define SM_U64_TOTAL 14464
#define SM_BYTES (SM_U64_TOTAL * 8)   // 115712

// ---- packed f32x2 + misc helpers ----
__device__ __forceinline__ u64 pk2(float lo, float hi) {
    u64 r; asm("mov.b64 %0, {%1, %2};" : "=l"(r) : "f"(lo), "f"(hi)); return r;
}
__device__ __forceinline__ void up2(u64 v, float& lo, float& hi) {
    asm("mov.b64 {%0, %1}, %2;" : "=f"(lo), "=f"(hi) : "l"(v));
}
__device__ __forceinline__ u64 fma2(u64 a, u64 b, u64 c) {
    u64 d; asm("fma.rn.f32x2 %0, %1, %2, %3;" : "=l"(d) : "l"(a), "l"(b), "l"(c)); return d;
}
__device__ __forceinline__ u64 add2(u64 a, u64 b) {
    u64 d; asm("add.rn.f32x2 %0, %1, %2;" : "=l"(d) : "l"(a), "l"(b)); return d;
}
__device__ __forceinline__ u64 mul2(u64 a, u64 b) {
    u64 d; asm("mul.rn.f32x2 %0, %1, %2;" : "=l"(d) : "l"(a), "l"(b)); return d;
}
__device__ __forceinline__ float ex2a(float x) {
    float r; asm("ex2.approx.ftz.f32 %0, %1;" : "=f"(r) : "f"(x)); return r;
}
__device__ __forceinline__ float rcpa(float x) {
    float r; asm("rcp.approx.ftz.f32 %0, %1;" : "=f"(r) : "f"(x)); return r;
}
__device__ __forceinline__ void cp_async16(void* dst, const void* src) {
    unsigned sdst = (unsigned)__cvta_generic_to_shared(dst);
    asm volatile("cp.async.cg.shared.global [%0], [%1], 16;" :: "r"(sdst), "l"(src));
}
__device__ __forceinline__ void cp_commit() {
    asm volatile("cp.async.commit_group;" ::: "memory");
}
__device__ __forceinline__ void cp_wait0() {
    asm volatile("cp.async.wait_group 0;" ::: "memory");
}
__device__ __forceinline__ void red_shared_f32(void* p, float v) {
    unsigned sa = (unsigned)__cvta_generic_to_shared(p);
    asm volatile("red.shared.add.f32 [%0], %1;" :: "r"(sa), "f"(v) : "memory");
}

// stage a 32x16x8-float tile (K or V): 1024 16B chunks, 4 per thread (NT=256)
__device__ __forceinline__ void stage_async(float* dst, const float* src0, int t) {
    #pragma unroll
    for (int i = 0; i < 4; ++i) {
        int c = t + NT * i;                     // chunk id 0..1023
        int r = c >> 1;                         // row = g*16 + d
        const float* src = src0 + ((size_t)(r >> 4) * HDIM + (r & 15)) * SLEN + 4 * (c & 1);
        cp_async16(dst + 4 * c, src);
    }
}

// Q staging by threads t<128 (lane=g row, w4=d offset)
__device__ __forceinline__ void load_q_ldg(ulonglong2* qA, ulonglong2* qB,
                                           const float* gq, int lane, int w4) {
    #pragma unroll
    for (int i = 0; i < 4; ++i) {
        int d = w4 + 4 * i;
        const float* src = gq + ((size_t)lane * HDIM + d) * SLEN;
        qA[i] = *(const ulonglong2*)(src);
        qB[i] = *(const ulonglong2*)(src + 4);
    }
}
__device__ __forceinline__ void sts_q(u64* sQ, const ulonglong2* qA, const ulonglong2* qB,
                                      int lane, int w4) {
    #pragma unroll
    for (int i = 0; i < 4; ++i) {
        int d = w4 + 4 * i;
        u64* dst = sQ + (size_t)(d * 4) * 32 + lane;
        dst[0] = qA[i].x; dst[32] = qA[i].y; dst[64] = qB[i].x; dst[96] = qB[i].y;
    }
}

__global__ void __launch_bounds__(NT, 2)
sdpa_group_kernel(const float* __restrict__ q, const float* __restrict__ k,
                  const float* __restrict__ v, float* __restrict__ out)
{
    extern __shared__ u64 sm[];
    u64*   sQ   = sm + SQ_U64;
    u64*   eX   = sm + SQ_U64;     // probs exchange (sQ+sK overlay, B2->B4)
    u64*   xSt  = sm + SQ_U64;     // x staging (sQ overlay, B4->B5)
    float* sK   = (float*)(sm + SK_U64);
    float* sV   = (float*)(sm + SV_U64);
    u64*   sL   = sm + SL_U64;
    u64*   sA   = sm + SA_U64;
    u64*   sSum = sm + SSUM_U64;

    const int t    = threadIdx.x;
    const int lane = t & 31;
    const int warp = t >> 5;
    const int g    = lane;
    const int sp   = warp & 3;           // s-pair: s = 2sp, 2sp+1
    const int fh   = warp >> 2;          // f-half: f in [16*fh, 16*fh+16)
    const int f0   = fh * 16;
    const int d0   = fh * 8;             // d-half owned in the x phase
    const int gb   = lane & 7;           // x-phase: g-block of 4 (g = 4gb..4gb+3)
    const int db   = lane >> 3;          // x-phase: d-pair (d = d0+2db, d0+2db+1)
    const int s0   = blockIdx.x * STILE;
    const int b    = blockIdx.y;
    const bool qstager = (t < 128);
    const int w4 = warp & 3;

    const size_t base = (size_t)b * (GQ * HDIM) * SLEN + (size_t)s0;
    const float L2E = 1.4426950408889634f;

    // ---- prologue ----
    stage_async(sK, k + base, t);
    stage_async(sV, v + base, t);
    cp_commit();
    ulonglong2 qA[4], qB[4];
    if (qstager) load_q_ldg(qA, qB, q + base, lane, w4);
    #pragma unroll 4
    for (int i = t; i < 8320; i += NT) sL[i] = 0ull;     // sL,sA,sSum contiguous
    if (qstager) sts_q(sQ, qA, qB, lane, w4);

    const u64 sc = pk2(0.25f * L2E, 0.25f * L2E);        // dk^-0.5 * log2(e)

    #pragma unroll 1
    for (int h = 0; h < NH; ++h) {
        cp_wait0();              // K(h), V(h) arrived
        __syncthreads();         // B1: tiles + Q(h) visible

        // early LDG of Q(h+1), held in regs until after B5
        if (qstager && h < NH - 1)
            load_q_ldg(qA, qB, q + base + (size_t)(h + 1) * DK * SLEN, lane, w4);

        // ---- qv = Q[g, :, s-pair] * scale ----
        u64 qv[DK];
        {
            const u64* qp = sQ + sp * 32 + g;
            #pragma unroll
            for (int d = 0; d < DK; ++d) qv[d] = mul2(qp[d * 128], sc);
        }

        // ---- logits for this f-half (log2 domain) ----
        u64 lg[16];
        #pragma unroll
        for (int fi = 0; fi < 16; ++fi) {
            const float* kb = sK + (f0 + fi) * 128 + 2 * sp;
            u64 a0 = mul2(qv[0], *(const u64*)(kb));
            u64 a1 = mul2(qv[1], *(const u64*)(kb + 8));
            #pragma unroll
            for (int d = 2; d < DK; d += 2) {
                a0 = fma2(qv[d],     *(const u64*)(kb + 8 * d),     a0);
                a1 = fma2(qv[d + 1], *(const u64*)(kb + 8 * d + 8), a1);
            }
            lg[fi] = add2(a0, a1);
        }

        // ---- accumulate logits sums ----
        u64* Lr = sL + (sp * 32 + f0) * 32 + g;
        #pragma unroll
        for (int fi = 0; fi < 16; ++fi) {
            u64* p = Lr + fi * 32;
            *p = add2(*p, lg[fi]);
        }

        // ---- exp2 + half-sum via red.shared (exactly 2 adds/slot) ----
        #pragma unroll
        for (int fi = 0; fi < 16; ++fi) {
            float a, bb; up2(lg[fi], a, bb);
            lg[fi] = pk2(ex2a(a), ex2a(bb));
        }
        {
            u64 ss[8];
            #pragma unroll
            for (int i = 0; i < 8; ++i) ss[i] = add2(lg[2 * i], lg[2 * i + 1]);
            #pragma unroll
            for (int i = 0; i < 4; ++i) ss[i] = add2(ss[2 * i], ss[2 * i + 1]);
            u64 psum = add2(add2(ss[0], ss[1]), add2(ss[2], ss[3]));
            float p0, p1; up2(psum, p0, p1);
            float* slot = (float*)(sSum + sp * 32 + g);
            red_shared_f32(slot,     p0);
            red_shared_f32(slot + 1, p1);
        }

        __syncthreads();         // B2: logits done (sQ, sK dead), sums complete

        // ---- rn; normalize; accumulate attn sums; post probs to eX ----
        {
            float sum0, sum1; up2(sSum[sp * 32 + g], sum0, sum1);
            const u64 rn = pk2(rcpa(sum0), rcpa(sum1));
            u64* Ar = sA + (sp * 32 + f0) * 32 + g;
            u64* Er = eX + (sp * 32 + f0) * 32 + g;
            #pragma unroll
            for (int fi = 0; fi < 16; ++fi) {
                lg[fi] = mul2(lg[fi], rn);
                u64* p = Ar + fi * 32;
                *p = add2(*p, lg[fi]);
                Er[fi * 32] = lg[fi];
            }
        }
        __syncthreads();         // B3: probs posted, sSum reads done

        if (t < 128) sSum[t] = 0ull;   // reset for next h (next adds after B1)

        // ---- x phase (register-tiled): lane owns (2 d) x (4 g), all 32 f ----
        // xv[dd][gi]: d = d0 + 2*db + dd, g2 = 4*gb + gi, s-pair = sp
        u64 xv0[4], xv1[4];
        {
            const u64* eXb  = eX + (sp * 32) * 32 + 4 * gb;      // f stride 32
            const float* vb = sV + (d0 + 2 * db) * 8 + 2 * sp;   // f stride 128
            {
                ulonglong2 pA = *(const ulonglong2*)(eXb);
                ulonglong2 pB = *(const ulonglong2*)(eXb + 2);
                u64 v0 = *(const u64*)(vb);
                u64 v1 = *(const u64*)(vb + 8);
                xv0[0] = mul2(pA.x, v0); xv0[1] = mul2(pA.y, v0);
                xv0[2] = mul2(pB.x, v0); xv0[3] = mul2(pB.y, v0);
                xv1[0] = mul2(pA.x, v1); xv1[1] = mul2(pA.y, v1);
                xv1[2] = mul2(pB.x, v1); xv1[3] = mul2(pB.y, v1);
            }
            #pragma unroll
            for (int f = 1; f < GQ; ++f) {
                ulonglong2 pA = *(const ulonglong2*)(eXb + f * 32);
                ulonglong2 pB = *(const ulonglong2*)(eXb + f * 32 + 2);
                u64 v0 = *(const u64*)(vb + f * 128);
                u64 v1 = *(const u64*)(vb + f * 128 + 8);
                xv0[0] = fma2(pA.x, v0, xv0[0]); xv0[1] = fma2(pA.y, v0, xv0[1]);
                xv0[2] = fma2(pB.x, v0, xv0[2]); xv0[3] = fma2(pB.y, v0, xv0[3]);
                xv1[0] = fma2(pA.x, v1, xv1[0]); xv1[1] = fma2(pA.y, v1, xv1[1]);
                xv1[2] = fma2(pB.x, v1, xv1[2]); xv1[3] = fma2(pB.y, v1, xv1[3]);
            }
        }
        __syncthreads();         // B4: x-FMAs done everywhere (eX, sV, sK dead)

        // prefetch K(h+1), V(h+1)
        if (h < NH - 1) {
            stage_async(sK, k + base + (size_t)(h + 1) * DK * SLEN, t);
            stage_async(sV, v + base + (size_t)(h + 1) * DK * SLEN, t);
            cp_commit();
        }

        // ---- stage x into xSt [(sp*16+d)*32+g] via STS.128 ----
        {
            int d = d0 + 2 * db;
            u64* p0 = xSt + (sp * 16 + d)     * 32 + 4 * gb;
            u64* p1 = xSt + (sp * 16 + d + 1) * 32 + 4 * gb;
            ulonglong2 a, c;
            a.x = xv0[0]; a.y = xv0[1]; *(ulonglong2*)p0 = a;
            a.x = xv0[2]; a.y = xv0[3]; *(ulonglong2*)(p0 + 2) = a;
            c.x = xv1[0]; c.y = xv1[1]; *(ulonglong2*)p1 = c;
            c.x = xv1[2]; c.y = xv1[3]; *(ulonglong2*)(p1 + 2) = c;
        }
        __syncthreads();         // B4.5: x staged

        // ---- cooperative coalesced STG: row (g,d) = 32B, 2 lanes per row ----
        #pragma unroll
        for (int i = 0; i < 4; ++i) {
            int u    = t + NT * i;        // 0..1023 units of 16B
            int r    = u >> 1;
            int half = u & 1;
            int dd   = r >> 5;
            int g2   = r & 31;
            u64 lo = xSt[((2 * half)     * 16 + dd) * 32 + g2];
            u64 hi = xSt[((2 * half + 1) * 16 + dd) * 32 + g2];
            float* dst = out + ((size_t)((b * GQ + g2) * HDIM) + (size_t)h * DK + dd) * SLEN
                             + (size_t)s0 + 4 * half;
            ulonglong2 val; val.x = lo; val.y = hi;
            *(ulonglong2*)dst = val;
        }
        __syncthreads();         // B5: staging reads done -> region free for Q(h+1)

        if (qstager && h < NH - 1) sts_q(sQ, qA, qB, lane, w4);
    }

    // ---- writeout head means ----
    __syncthreads();
    const size_t AOFF = (size_t)B_SZ * GQ * HDIM * SLEN;       // 33554432
    const size_t LOFF = AOFF + (size_t)B_SZ * GQ * GQ * SLEN;  // 41943040
    const u64 cA = pk2(0.125f, 0.125f);
    const float lsc = 0.125f / L2E;                            // undo log2-domain
    const u64 cL = pk2(lsc, lsc);
    #pragma unroll
    for (int i = 0; i < 4; ++i) {
        int r  = t + NT * i;      // 0..1023
        int f  = r & 31;
        int gg = r >> 5;
        size_t o = ((size_t)(b * GQ + gg) * GQ + f) * SLEN + (size_t)s0;
        #pragma unroll
        for (int sp2 = 0; sp2 < 4; ++sp2) {
            int idx = (sp2 * 32 + f) * 32 + gg;
            *(u64*)(out + AOFF + o + 2 * sp2) = mul2(sA[idx], cA);
            *(u64*)(out + LOFF + o + 2 * sp2) = mul2(sL[idx], cL);
        }
    }
}

extern "C" void kernel_launch(void* const* d_in, const int* in_sizes, int n_in,
                              void* d_out, int out_size)
{
    const float* q = (const float*)d_in[0];
    const float* k = (const float*)d_in[1];
    const float* v = (const float*)d_in[2];
    float* out = (float*)d_out;

    cudaFuncSetAttribute(sdpa_group_kernel,
                         cudaFuncAttributeMaxDynamicSharedMemorySize, SM_BYTES);

    dim3 grid(SLEN / STILE, B_SZ);
    sdpa_group_kernel<<<grid, NT, SM_BYTES>>>(q, k, v, out);
}

// round 12
// speedup vs baseline: 1.1720x; 1.1720x over previous
#include <cuda_runtime.h>
#include <cstdint>

#define B_SZ  2
#define GQ    32
#define HDIM  128
#define NH    8
#define DK    16
#define SLEN  4096
#define STILE 8
#define NT    256

typedef unsigned long long u64;

// SMEM (u64 units), total 14464 u64 = 115712 B -> 2 CTAs/SM:
//  sQ   [0,2048)      u64[(d*4+sp)*32 + g]        (Q tile; dead after B2)
//  sK   [2048,4096)   float[f*128 + d*8 + s]      (K tile; dead after B2)
//    eX  = [0,4096)   u64[(sp*32+f)*32 + g]       probs exchange (B2->B4)
//    xSt = [0,2048)   u64[(sp*16+d)*32 + g]       x staging (B4->B5)
//  sV   [4096,6144)   float[f*128 + d*8 + s]      (V tile; dead after B4)
//  sL   [6144,10240)  u64[(sp*32+f)*32 + g]       logits sums over h
//  sA   [10240,14336) same                        attn sums over h
//  sSum [14336,14464) u64[sp*32 + g]              softmax totals (red.shared,
//                     exactly 2 adds/slot -> deterministic; zeroed post-B3)
#define SQ_U64   0
#define SK_U64   2048
#define SV_U64   4096
#define SL_U64   6144
#define SA_U64   10240
#define SSUM_U64 14336
#define SM_U64_TOTAL 14464
#define SM_BYTES (SM_U64_TOTAL * 8)   // 115712

// ---- packed f32x2 + misc helpers ----
__device__ __forceinline__ u64 pk2(float lo, float hi) {
    u64 r; asm("mov.b64 %0, {%1, %2};" : "=l"(r) : "f"(lo), "f"(hi)); return r;
}
__device__ __forceinline__ void up2(u64 v, float& lo, float& hi) {
    asm("mov.b64 {%0, %1}, %2;" : "=f"(lo), "=f"(hi) : "l"(v));
}
__device__ __forceinline__ u64 fma2(u64 a, u64 b, u64 c) {
    u64 d; asm("fma.rn.f32x2 %0, %1, %2, %3;" : "=l"(d) : "l"(a), "l"(b), "l"(c)); return d;
}
__device__ __forceinline__ u64 add2(u64 a, u64 b) {
    u64 d; asm("add.rn.f32x2 %0, %1, %2;" : "=l"(d) : "l"(a), "l"(b)); return d;
}
__device__ __forceinline__ u64 mul2(u64 a, u64 b) {
    u64 d; asm("mul.rn.f32x2 %0, %1, %2;" : "=l"(d) : "l"(a), "l"(b)); return d;
}
__device__ __forceinline__ float ex2a(float x) {
    float r; asm("ex2.approx.ftz.f32 %0, %1;" : "=f"(r) : "f"(x)); return r;
}
__device__ __forceinline__ float rcpa(float x) {
    float r; asm("rcp.approx.ftz.f32 %0, %1;" : "=f"(r) : "f"(x)); return r;
}
__device__ __forceinline__ void cp_async16(void* dst, const void* src) {
    unsigned sdst = (unsigned)__cvta_generic_to_shared(dst);
    asm volatile("cp.async.cg.shared.global [%0], [%1], 16;" :: "r"(sdst), "l"(src));
}
__device__ __forceinline__ void cp_commit() {
    asm volatile("cp.async.commit_group;" ::: "memory");
}
__device__ __forceinline__ void cp_wait0() {
    asm volatile("cp.async.wait_group 0;" ::: "memory");
}
__device__ __forceinline__ void red_shared_f32(void* p, float v) {
    unsigned sa = (unsigned)__cvta_generic_to_shared(p);
    asm volatile("red.shared.add.f32 [%0], %1;" :: "r"(sa), "f"(v) : "memory");
}

// stage a 32x16x8-float tile (K or V): 1024 16B chunks, 4 per thread (NT=256)
__device__ __forceinline__ void stage_async(float* dst, const float* src0, int t) {
    #pragma unroll
    for (int i = 0; i < 4; ++i) {
        int c = t + NT * i;                     // chunk id 0..1023
        int r = c >> 1;                         // row = g*16 + d
        const float* src = src0 + ((size_t)(r >> 4) * HDIM + (r & 15)) * SLEN + 4 * (c & 1);
        cp_async16(dst + 4 * c, src);
    }
}

// Q staging by threads t<128 (lane=g row, w4=d offset)
__device__ __forceinline__ void load_q_ldg(ulonglong2* qA, ulonglong2* qB,
                                           const float* gq, int lane, int w4) {
    #pragma unroll
    for (int i = 0; i < 4; ++i) {
        int d = w4 + 4 * i;
        const float* src = gq + ((size_t)lane * HDIM + d) * SLEN;
        qA[i] = *(const ulonglong2*)(src);
        qB[i] = *(const ulonglong2*)(src + 4);
    }
}
__device__ __forceinline__ void sts_q(u64* sQ, const ulonglong2* qA, const ulonglong2* qB,
                                      int lane, int w4) {
    #pragma unroll
    for (int i = 0; i < 4; ++i) {
        int d = w4 + 4 * i;
        u64* dst = sQ + (size_t)(d * 4) * 32 + lane;
        dst[0] = qA[i].x; dst[32] = qA[i].y; dst[64] = qB[i].x; dst[96] = qB[i].y;
    }
}

__global__ void __launch_bounds__(NT, 2)
sdpa_group_kernel(const float* __restrict__ q, const float* __restrict__ k,
                  const float* __restrict__ v, float* __restrict__ out)
{
    extern __shared__ u64 sm[];
    u64*   sQ   = sm + SQ_U64;
    u64*   eX   = sm + SQ_U64;     // probs exchange (sQ+sK overlay, B2->B4)
    u64*   xSt  = sm + SQ_U64;     // x staging (sQ overlay, B4->B5)
    float* sK   = (float*)(sm + SK_U64);
    float* sV   = (float*)(sm + SV_U64);
    u64*   sL   = sm + SL_U64;
    u64*   sA   = sm + SA_U64;
    u64*   sSum = sm + SSUM_U64;

    const int t    = threadIdx.x;
    const int lane = t & 31;
    const int warp = t >> 5;
    const int g    = lane;
    const int sp   = warp & 3;           // s-pair: s = 2sp, 2sp+1
    const int fh   = warp >> 2;          // f-half: f in [16*fh, 16*fh+16)
    const int f0   = fh * 16;
    const int d0   = fh * 8;             // d-half owned in the x phase
    const int gb   = lane & 7;           // x-phase g-slot: g in {2gb,2gb+1,2gb+16,2gb+17}
    const int db   = lane >> 3;          // x-phase d-slot: d in {d0+db, d0+db+4}
    const int s0   = blockIdx.x * STILE;
    const int b    = blockIdx.y;
    const bool qstager = (t < 128);
    const int w4 = warp & 3;

    const size_t base = (size_t)b * (GQ * HDIM) * SLEN + (size_t)s0;
    const float L2E = 1.4426950408889634f;

    // ---- prologue ----
    stage_async(sK, k + base, t);
    stage_async(sV, v + base, t);
    cp_commit();
    ulonglong2 qA[4], qB[4];
    if (qstager) load_q_ldg(qA, qB, q + base, lane, w4);
    #pragma unroll 4
    for (int i = t; i < 8320; i += NT) sL[i] = 0ull;     // sL,sA,sSum contiguous
    if (qstager) sts_q(sQ, qA, qB, lane, w4);

    const u64 sc = pk2(0.25f * L2E, 0.25f * L2E);        // dk^-0.5 * log2(e)

    #pragma unroll 1
    for (int h = 0; h < NH; ++h) {
        cp_wait0();              // K(h), V(h) arrived
        __syncthreads();         // B1: tiles + Q(h) visible

        // early LDG of Q(h+1), held in regs until after B5
        if (qstager && h < NH - 1)
            load_q_ldg(qA, qB, q + base + (size_t)(h + 1) * DK * SLEN, lane, w4);

        // ---- qv = Q[g, :, s-pair] * scale ----
        u64 qv[DK];
        {
            const u64* qp = sQ + sp * 32 + g;
            #pragma unroll
            for (int d = 0; d < DK; ++d) qv[d] = mul2(qp[d * 128], sc);
        }

        // ---- logits for this f-half (log2 domain) ----
        u64 lg[16];
        #pragma unroll
        for (int fi = 0; fi < 16; ++fi) {
            const float* kb = sK + (f0 + fi) * 128 + 2 * sp;
            u64 a0 = mul2(qv[0], *(const u64*)(kb));
            u64 a1 = mul2(qv[1], *(const u64*)(kb + 8));
            #pragma unroll
            for (int d = 2; d < DK; d += 2) {
                a0 = fma2(qv[d],     *(const u64*)(kb + 8 * d),     a0);
                a1 = fma2(qv[d + 1], *(const u64*)(kb + 8 * d + 8), a1);
            }
            lg[fi] = add2(a0, a1);
        }

        // ---- accumulate logits sums ----
        u64* Lr = sL + (sp * 32 + f0) * 32 + g;
        #pragma unroll
        for (int fi = 0; fi < 16; ++fi) {
            u64* p = Lr + fi * 32;
            *p = add2(*p, lg[fi]);
        }

        // ---- exp2 + half-sum via red.shared (exactly 2 adds/slot) ----
        #pragma unroll
        for (int fi = 0; fi < 16; ++fi) {
            float a, bb; up2(lg[fi], a, bb);
            lg[fi] = pk2(ex2a(a), ex2a(bb));
        }
        {
            u64 ss[8];
            #pragma unroll
            for (int i = 0; i < 8; ++i) ss[i] = add2(lg[2 * i], lg[2 * i + 1]);
            #pragma unroll
            for (int i = 0; i < 4; ++i) ss[i] = add2(ss[2 * i], ss[2 * i + 1]);
            u64 psum = add2(add2(ss[0], ss[1]), add2(ss[2], ss[3]));
            float p0, p1; up2(psum, p0, p1);
            float* slot = (float*)(sSum + sp * 32 + g);
            red_shared_f32(slot,     p0);
            red_shared_f32(slot + 1, p1);
        }

        __syncthreads();         // B2: logits done (sQ, sK dead), sums complete

        // ---- rn; normalize; accumulate attn sums; post probs to eX ----
        {
            float sum0, sum1; up2(sSum[sp * 32 + g], sum0, sum1);
            const u64 rn = pk2(rcpa(sum0), rcpa(sum1));
            u64* Ar = sA + (sp * 32 + f0) * 32 + g;
            u64* Er = eX + (sp * 32 + f0) * 32 + g;
            #pragma unroll
            for (int fi = 0; fi < 16; ++fi) {
                lg[fi] = mul2(lg[fi], rn);
                u64* p = Ar + fi * 32;
                *p = add2(*p, lg[fi]);
                Er[fi * 32] = lg[fi];
            }
        }
        __syncthreads();         // B3: probs posted, sSum reads done

        if (t < 128) sSum[t] = 0ull;   // reset for next h (next adds after B1)

        // ---- x phase (register-tiled, conflict-free):
        //      lane owns d in {d0+db, d0+db+4}, g in {2gb,2gb+1,2gb+16,2gb+17} ----
        u64 xa[4], xb[4];        // [d0+db][4g], [d0+db+4][4g]
        {
            const u64* er0 = eX + (sp * 32) * 32 + 2 * gb;       // f stride 32 u64
            const float* vf0 = sV + (d0 + db) * 8 + 2 * sp;      // f stride 128 fl
            {
                ulonglong2 pA = *(const ulonglong2*)(er0);        // g=2gb,2gb+1
                ulonglong2 pB = *(const ulonglong2*)(er0 + 16);   // g=2gb+16,2gb+17
                u64 va = *(const u64*)(vf0);                      // d=d0+db
                u64 vb = *(const u64*)(vf0 + 32);                 // d=d0+db+4
                xa[0] = mul2(pA.x, va); xa[1] = mul2(pA.y, va);
                xa[2] = mul2(pB.x, va); xa[3] = mul2(pB.y, va);
                xb[0] = mul2(pA.x, vb); xb[1] = mul2(pA.y, vb);
                xb[2] = mul2(pB.x, vb); xb[3] = mul2(pB.y, vb);
            }
            #pragma unroll
            for (int f = 1; f < GQ; ++f) {
                const u64* er = er0 + f * 32;
                const float* vf = vf0 + f * 128;
                ulonglong2 pA = *(const ulonglong2*)(er);
                ulonglong2 pB = *(const ulonglong2*)(er + 16);
                u64 va = *(const u64*)(vf);
                u64 vb = *(const u64*)(vf + 32);
                xa[0] = fma2(pA.x, va, xa[0]); xa[1] = fma2(pA.y, va, xa[1]);
                xa[2] = fma2(pB.x, va, xa[2]); xa[3] = fma2(pB.y, va, xa[3]);
                xb[0] = fma2(pA.x, vb, xb[0]); xb[1] = fma2(pA.y, vb, xb[1]);
                xb[2] = fma2(pB.x, vb, xb[2]); xb[3] = fma2(pB.y, vb, xb[3]);
            }
        }
        __syncthreads();         // B4: x-FMAs done everywhere (eX, sV, sK dead)

        // prefetch K(h+1), V(h+1)
        if (h < NH - 1) {
            stage_async(sK, k + base + (size_t)(h + 1) * DK * SLEN, t);
            stage_async(sV, v + base + (size_t)(h + 1) * DK * SLEN, t);
            cp_commit();
        }

        // ---- stage x into xSt [(sp*16+d)*32+g] via STS.128 ----
        {
            u64* ra = xSt + (sp * 16 + d0 + db)     * 32 + 2 * gb;
            u64* rb = xSt + (sp * 16 + d0 + db + 4) * 32 + 2 * gb;
            ulonglong2 w;
            w.x = xa[0]; w.y = xa[1]; *(ulonglong2*)ra = w;
            w.x = xa[2]; w.y = xa[3]; *(ulonglong2*)(ra + 16) = w;
            w.x = xb[0]; w.y = xb[1]; *(ulonglong2*)rb = w;
            w.x = xb[2]; w.y = xb[3]; *(ulonglong2*)(rb + 16) = w;
        }
        __syncthreads();         // B4.5: x staged

        // ---- cooperative coalesced STG: row (g,d) = 32B, 2 lanes per row ----
        #pragma unroll
        for (int i = 0; i < 4; ++i) {
            int u    = t + NT * i;        // 0..1023 units of 16B
            int r    = u >> 1;
            int half = u & 1;
            int dd   = r >> 5;
            int g2   = r & 31;
            u64 lo = xSt[((2 * half)     * 16 + dd) * 32 + g2];
            u64 hi = xSt[((2 * half + 1) * 16 + dd) * 32 + g2];
            float* dst = out + ((size_t)((b * GQ + g2) * HDIM) + (size_t)h * DK + dd) * SLEN
                             + (size_t)s0 + 4 * half;
            ulonglong2 val; val.x = lo; val.y = hi;
            *(ulonglong2*)dst = val;
        }
        __syncthreads();         // B5: staging reads done -> region free for Q(h+1)

        if (qstager && h < NH - 1) sts_q(sQ, qA, qB, lane, w4);
    }

    // ---- writeout head means ----
    __syncthreads();
    const size_t AOFF = (size_t)B_SZ * GQ * HDIM * SLEN;       // 33554432
    const size_t LOFF = AOFF + (size_t)B_SZ * GQ * GQ * SLEN;  // 41943040
    const u64 cA = pk2(0.125f, 0.125f);
    const float lsc = 0.125f / L2E;                            // undo log2-domain
    const u64 cL = pk2(lsc, lsc);
    #pragma unroll
    for (int i = 0; i < 4; ++i) {
        int r  = t + NT * i;      // 0..1023
        int f  = r & 31;
        int gg = r >> 5;
        size_t o = ((size_t)(b * GQ + gg) * GQ + f) * SLEN + (size_t)s0;
        #pragma unroll
        for (int sp2 = 0; sp2 < 4; ++sp2) {
            int idx = (sp2 * 32 + f) * 32 + gg;
            *(u64*)(out + AOFF + o + 2 * sp2) = mul2(sA[idx], cA);
            *(u64*)(out + LOFF + o + 2 * sp2) = mul2(sL[idx], cL);
        }
    }
}

extern "C" void kernel_launch(void* const* d_in, const int* in_sizes, int n_in,
                              void* d_out, int out_size)
{
    const float* q = (const float*)d_in[0];
    const float* k = (const float*)d_in[1];
    const float* v = (const float*)d_in[2];
    float* out = (float*)d_out;

    cudaFuncSetAttribute(sdpa_group_kernel,
                         cudaFuncAttributeMaxDynamicSharedMemorySize, SM_BYTES);

    dim3 grid(SLEN / STILE, B_SZ);
    sdpa_group_kernel<<<grid, NT, SM_BYTES>>>(q, k, v, out);
}